// round 5
// baseline (speedup 1.0000x reference)
#include <cuda_runtime.h>
#include <cstdint>

// Packed f32x2 FMA / ADD — only reachable via PTX (ptxas never auto-fuses).
#define FMA2(d, a, b, c) \
    asm("fma.rn.f32x2 %0, %1, %2, %3;" : "=l"(d) : "l"(a), "l"(b), "l"(c))
#define ADD2(d, a, b) \
    asm("add.rn.f32x2 %0, %1, %2;" : "=l"(d) : "l"(a), "l"(b))

__device__ __forceinline__ unsigned long long pack2(float lo, float hi) {
    unsigned long long r;
    asm("mov.b64 %0, {%1, %2};" : "=l"(r) : "f"(lo), "f"(hi));
    return r;
}

namespace {
constexpr int H  = 224;
constexpr int W  = 224;
constexpr int HO = 222;
constexpr int WO = 222;
constexpr int OC = 64;
constexpr int TPB = 224;   // 2 rows x 112 pair-slots (111 active)
}

// Block: 2 output rows x 222 cols x 32 channels x 1 batch.
// Thread: 1 row x 2 cols (one packed pair) x 32 channels.
// Grid (111, 2, 32) = 7104 blocks = 1.59M threads.
__global__ __launch_bounds__(TPB, 6)
void Conv2d_68298569941797_kernel(const float* __restrict__ data,
                                  const float* __restrict__ weight,
                                  float* __restrict__ out) {
    __shared__ float s_in[4 * W];                 // input rows y0..y0+3
    __shared__ unsigned long long s_w[OC * 10];   // 9 packed (w,w) + pad per channel

    const int tid = threadIdx.x;
    const int b   = blockIdx.z;
    const int y0  = blockIdx.x * 2;

    // Stage 4 input rows (y0 <= 220 -> rows <= 223, in bounds).
    const float* src = data + ((size_t)b * H + y0) * W;
    for (int i = tid; i < 4 * W; i += TPB) s_in[i] = src[i];

    // Stage all 64 channels' weights packed (w,w); this block reads 32 of them.
    for (int i = tid; i < OC * 9; i += TPB) {
        int o = i / 9;
        int k = i - o * 9;
        float w = weight[i];
        s_w[o * 10 + k] = pack2(w, w);
    }
    __syncthreads();

    const int r = tid / 112;          // output row within block
    const int s = tid - r * 112;      // pair slot
    if (s >= 111) return;             // 111 pairs cover WO=222 exactly
    const int x = 2 * s;

    // 9 packed sliding-pair operands: rows r..r+2, cols x..x+3.
    const float* rowp = s_in + r * W + x;
    unsigned long long P[9];
#pragma unroll
    for (int rr = 0; rr < 3; ++rr) {
        float a0 = rowp[rr * W + 0];
        float a1 = rowp[rr * W + 1];
        float a2 = rowp[rr * W + 2];
        float a3 = rowp[rr * W + 3];
        P[rr * 3 + 0] = pack2(a0, a1);
        P[rr * 3 + 1] = pack2(a1, a2);
        P[rr * 3 + 2] = pack2(a2, a3);
    }

    const int cbase = blockIdx.y * 32;
    const size_t plane = (size_t)HO * WO;
    float* op = out + (((size_t)b * OC + cbase) * HO + (y0 + r)) * WO + x;
    const ulonglong2* w2 = reinterpret_cast<const ulonglong2*>(s_w) + (size_t)cbase * 5;

#pragma unroll 2
    for (int o = 0; o < 32; ++o) {
        const ulonglong2* wo = w2 + o * 5;
        ulonglong2 w01 = wo[0];
        ulonglong2 w23 = wo[1];
        ulonglong2 w45 = wo[2];
        ulonglong2 w67 = wo[3];
        ulonglong2 w8x = wo[4];   // .y is padding

        // Two independent chains (5 + 4) -> halved dependency depth.
        unsigned long long Aa = 0ull, Ab = 0ull;
        FMA2(Aa, P[0], w01.x, Aa);
        FMA2(Ab, P[1], w01.y, Ab);
        FMA2(Aa, P[2], w23.x, Aa);
        FMA2(Ab, P[3], w23.y, Ab);
        FMA2(Aa, P[4], w45.x, Aa);
        FMA2(Ab, P[5], w45.y, Ab);
        FMA2(Aa, P[6], w67.x, Aa);
        FMA2(Ab, P[7], w67.y, Ab);
        FMA2(Aa, P[8], w8x.x, Aa);

        unsigned long long acc;
        ADD2(acc, Aa, Ab);

        *reinterpret_cast<unsigned long long*>(op) = acc;  // STG.64, coalesced
        op += plane;
    }
}

extern "C" void kernel_launch(void* const* d_in, const int* in_sizes, int n_in,
                              void* d_out, int out_size) {
    const float* data   = (const float*)d_in[0];
    const float* weight = (const float*)d_in[1];
    float* out          = (float*)d_out;

    dim3 grid(HO / 2, 2, 32);   // (111, 2, 32)
    Conv2d_68298569941797_kernel<<<grid, TPB>>>(data, weight, out);
}